// round 16
// baseline (speedup 1.0000x reference)
#include <cuda_runtime.h>
#include <cuda_fp16.h>
#include <math.h>
#include <stdint.h>

// Problem constants
constexpr int Bb  = 2;
constexpr int Ll  = 2048;
constexpr int Dd  = 512;
constexpr int Hh  = 8;
constexpr int HD  = 64;
constexpr int DH  = 2048;
constexpr int MREL = 128;
constexpr int D3  = 3 * Dd;    // 1536
constexpr int BL  = Bb * Ll;   // 4096
constexpr long long XSIZE  = (long long)BL * Dd;

// fp16 staging buffers
__device__ __half g_h16  [BL * Dd];
__device__ __half g_qkv16[BL * D3];
__device__ __half g_o16  [BL * Dd];
__device__ __half g_f16  [BL * DH];
// fp16 weights: qkv_w | out_w | ffn_in_w | ffn_out_w  (contiguous)
constexpr long long OFF_QKVW   = 0;
constexpr long long OFF_OUTW   = OFF_QKVW  + (long long)Dd * D3;
constexpr long long OFF_FFNIN  = OFF_OUTW  + (long long)Dd * Dd;
constexpr long long OFF_FFNOUT = OFF_FFNIN + (long long)Dd * 2 * DH;
constexpr long long W16_TOTAL  = OFF_FFNOUT + (long long)DH * Dd;   // 4,194,304
__device__ __half g_w16[W16_TOTAL];
__device__ float  g_x1  [BL * Dd];

// ---------------- helpers ----------------
static __device__ __forceinline__ uint32_t sm32(const void* p) {
    return (uint32_t)__cvta_generic_to_shared(p);
}
static __device__ __forceinline__ void cp16(void* dst, const void* src) {
    asm volatile("cp.async.cg.shared.global [%0], [%1], 16;\n"
                 :: "r"(sm32(dst)), "l"(__cvta_generic_to_global(src)));
}
static __device__ __forceinline__ void cp_commit() {
    asm volatile("cp.async.commit_group;\n");
}
template <int N> static __device__ __forceinline__ void cp_wait() {
    asm volatile("cp.async.wait_group %0;\n" :: "n"(N));
}
static __device__ __forceinline__ void ldsm_x4(uint32_t& r0, uint32_t& r1, uint32_t& r2, uint32_t& r3, uint32_t a) {
    asm volatile("ldmatrix.sync.aligned.m8n8.x4.shared.b16 {%0,%1,%2,%3}, [%4];\n"
                 : "=r"(r0), "=r"(r1), "=r"(r2), "=r"(r3) : "r"(a));
}
static __device__ __forceinline__ void ldsm_x4t(uint32_t& r0, uint32_t& r1, uint32_t& r2, uint32_t& r3, uint32_t a) {
    asm volatile("ldmatrix.sync.aligned.m8n8.x4.trans.shared.b16 {%0,%1,%2,%3}, [%4];\n"
                 : "=r"(r0), "=r"(r1), "=r"(r2), "=r"(r3) : "r"(a));
}
static __device__ __forceinline__ void ldsm_x2t(uint32_t& r0, uint32_t& r1, uint32_t a) {
    asm volatile("ldmatrix.sync.aligned.m8n8.x2.trans.shared.b16 {%0,%1}, [%2];\n"
                 : "=r"(r0), "=r"(r1) : "r"(a));
}
static __device__ __forceinline__ void mma16(float* c, const uint32_t* a, const uint32_t* b) {
    asm volatile("mma.sync.aligned.m16n8k16.row.col.f32.f16.f16.f32 "
                 "{%0,%1,%2,%3}, {%4,%5,%6,%7}, {%8,%9}, {%0,%1,%2,%3};\n"
                 : "+f"(c[0]), "+f"(c[1]), "+f"(c[2]), "+f"(c[3])
                 : "r"(a[0]), "r"(a[1]), "r"(a[2]), "r"(a[3]), "r"(b[0]), "r"(b[1]));
}
static __device__ __forceinline__ float ex2(float x) {
    float r;
    asm("ex2.approx.f32 %0, %1;" : "=f"(r) : "f"(x));
    return r;
}
static __device__ __forceinline__ void stcs2(float* p, float a, float b) {
    asm volatile("st.global.cs.v2.f32 [%0], {%1, %2};"
                 :: "l"(__cvta_generic_to_global(p)), "f"(a), "f"(b) : "memory");
}
static __device__ __forceinline__ int clampq(int d) {
    return d < -(MREL - 1) ? -(MREL - 1) : (d > (MREL - 1) ? (MREL - 1) : d);
}

// ---------------- merged: weights fp32->fp16 + LN1, one launch ----------------
constexpr long long E0 = OFF_OUTW   / 4;
constexpr long long E1 = OFF_FFNIN  / 4;
constexpr long long E2 = OFF_FFNOUT / 4;
constexpr long long E3 = W16_TOTAL  / 4;   // 1,048,576 -> 4096 blocks of 256
__global__ void f2h_ln_kernel(const float4* __restrict__ wa, const float4* __restrict__ wb,
                              const float4* __restrict__ wc, const float4* __restrict__ wd,
                              __half2* __restrict__ wdst,
                              const float* __restrict__ x, const float* __restrict__ lw,
                              const float* __restrict__ lb, __half* __restrict__ hout) {
    if (blockIdx.x < 4096) {
        long long i = (long long)blockIdx.x * 256 + threadIdx.x;
        const float4* src; long long off;
        if (i < E0)      { src = wa; off = 0;  }
        else if (i < E1) { src = wb; off = E0; }
        else if (i < E2) { src = wc; off = E1; }
        else             { src = wd; off = E2; }
        float4 v = src[i - off];
        wdst[i * 2]     = __floats2half2_rn(v.x, v.y);
        wdst[i * 2 + 1] = __floats2half2_rn(v.z, v.w);
        return;
    }
    int row = blockIdx.x - 4096;
    const float* xr = x + (long long)row * Dd;
    int t = threadIdx.x;
    float v0 = xr[t], v1 = xr[t + 256];
    __shared__ float red[256];
    red[t] = v0 + v1;
    __syncthreads();
    #pragma unroll
    for (int o = 128; o > 0; o >>= 1) { if (t < o) red[t] += red[t + o]; __syncthreads(); }
    float mu = red[0] * (1.0f / Dd);
    __syncthreads();
    float d0 = v0 - mu, d1 = v1 - mu;
    red[t] = d0 * d0 + d1 * d1;
    __syncthreads();
    #pragma unroll
    for (int o = 128; o > 0; o >>= 1) { if (t < o) red[t] += red[t + o]; __syncthreads(); }
    float rstd = rsqrtf(red[0] * (1.0f / Dd) + 1e-5f);
    __half* orow = hout + (long long)row * Dd;
    orow[t]       = __float2half(d0 * rstd * lw[t]       + lb[t]);
    orow[t + 256] = __float2half(d1 * rstd * lw[t + 256] + lb[t + 256]);
}

// ---------------- LayerNorm -> fp16 out ----------------
__global__ void ln_kernel(const float* __restrict__ x, const float* __restrict__ w,
                          const float* __restrict__ b, __half* __restrict__ out) {
    int row = blockIdx.x;
    const float* xr = x + (long long)row * Dd;
    int t = threadIdx.x;
    float v0 = xr[t], v1 = xr[t + 256];
    __shared__ float red[256];
    red[t] = v0 + v1;
    __syncthreads();
    #pragma unroll
    for (int o = 128; o > 0; o >>= 1) { if (t < o) red[t] += red[t + o]; __syncthreads(); }
    float mu = red[0] * (1.0f / Dd);
    __syncthreads();
    float d0 = v0 - mu, d1 = v1 - mu;
    red[t] = d0 * d0 + d1 * d1;
    __syncthreads();
    #pragma unroll
    for (int o = 128; o > 0; o >>= 1) { if (t < o) red[t] += red[t + o]; __syncthreads(); }
    float rstd = rsqrtf(red[0] * (1.0f / Dd) + 1e-5f);
    __half* orow = out + (long long)row * Dd;
    orow[t]       = __float2half(d0 * rstd * w[t]       + b[t]);
    orow[t + 256] = __float2half(d1 * rstd * w[t + 256] + b[t + 256]);
}

// ---------------- BM=128 GEMM, half out, 3-stage (QKV) ----------------
__global__ void gemm16_kernel(const __half* __restrict__ A, const __half* __restrict__ W,
                              const float* __restrict__ bias, __half* __restrict__ Ch,
                              int N, int K) {
    __shared__ __half As[3][128][40];
    __shared__ __half Bs[3][32][136];
    int bm = blockIdx.y * 128, bn = blockIdx.x * 128;
    int tid = threadIdx.x, lane = tid & 31, wid = tid >> 5;
    int wm0 = (wid & 1) * 64, wn0 = (wid >> 1) * 32;

    auto load = [&](int k0, int st) {
        #pragma unroll
        for (int i = 0; i < 2; i++) {
            int t = tid + i * 256;
            int r = t >> 2, s = t & 3;
            cp16(&As[st][r][s * 8], A + (size_t)(bm + r) * K + k0 + s * 8);
        }
        #pragma unroll
        for (int i = 0; i < 2; i++) {
            int t = tid + i * 256;
            int r = t >> 4, s = t & 15;
            cp16(&Bs[st][r][s * 8], W + (size_t)(k0 + r) * N + bn + s * 8);
        }
    };
    int nIter = K / 32;
    load(0, 0); cp_commit();
    if (nIter > 1) { load(32, 1); cp_commit(); }
    float acc[4][4][4] = {};
    for (int it = 0; it < nIter; it++) {
        int cur = it % 3;
        if (it + 2 < nIter) { load((it + 2) * 32, (it + 2) % 3); cp_commit(); cp_wait<2>(); }
        else if (it + 1 < nIter) cp_wait<1>();
        else cp_wait<0>();
        __syncthreads();
        #pragma unroll
        for (int ks = 0; ks < 32; ks += 16) {
            uint32_t a[4][4], b[4][2];
            #pragma unroll
            for (int i = 0; i < 4; i++)
                ldsm_x4(a[i][0], a[i][1], a[i][2], a[i][3],
                        sm32(&As[cur][wm0 + i * 16 + (lane & 15)][ks + (lane >> 4) * 8]));
            #pragma unroll
            for (int j = 0; j < 4; j++)
                ldsm_x2t(b[j][0], b[j][1], sm32(&Bs[cur][ks + (lane & 15)][wn0 + j * 8]));
            #pragma unroll
            for (int i = 0; i < 4; i++)
                #pragma unroll
                for (int j = 0; j < 4; j++) mma16(acc[i][j], a[i], b[j]);
        }
        __syncthreads();
    }
    #pragma unroll
    for (int i = 0; i < 4; i++) {
        #pragma unroll
        for (int j = 0; j < 4; j++) {
            int r = bm + wm0 + i * 16 + (lane >> 2);
            int c = bn + wn0 + j * 8 + (lane & 3) * 2;
            #pragma unroll
            for (int hh = 0; hh < 2; hh++) {
                size_t idx = (size_t)(r + hh * 8) * N + c;
                float v0 = acc[i][j][hh * 2]     + bias[c];
                float v1 = acc[i][j][hh * 2 + 1] + bias[c + 1];
                *(__half2*)(Ch + idx) = __floats2half2_rn(v0, v1);
            }
        }
    }
}

// ---------------- BM=64 GEMM for N=512, MODE1 epilogue, 3-stage, 3 CTAs/SM ----------------
// STREAM: use streaming stores for the final output (never re-read).
template <bool STREAM>
__global__ void __launch_bounds__(256, 3)
gemm16_n512_kernel(const __half* __restrict__ A, const __half* __restrict__ W,
                   const float* __restrict__ bias, float* __restrict__ Cf,
                   const float* __restrict__ resid, const float* __restrict__ gamma,
                   int N, int K) {
    __shared__ __half As[3][64][40];
    __shared__ __half Bs[3][32][136];
    int bm = blockIdx.y * 64, bn = blockIdx.x * 128;
    int tid = threadIdx.x, lane = tid & 31, wid = tid >> 5;
    int wm0 = (wid & 1) * 32, wn0 = (wid >> 1) * 32;

    auto load = [&](int k0, int st) {
        {
            int r = tid >> 2, s = tid & 3;
            cp16(&As[st][r][s * 8], A + (size_t)(bm + r) * K + k0 + s * 8);
        }
        #pragma unroll
        for (int i = 0; i < 2; i++) {
            int t = tid + i * 256;
            int r = t >> 4, s = t & 15;
            cp16(&Bs[st][r][s * 8], W + (size_t)(k0 + r) * N + bn + s * 8);
        }
    };
    int nIter = K / 32;
    load(0, 0); cp_commit();
    if (nIter > 1) { load(32, 1); cp_commit(); }
    float acc[2][4][4] = {};
    for (int it = 0; it < nIter; it++) {
        int cur = it % 3;
        if (it + 2 < nIter) { load((it + 2) * 32, (it + 2) % 3); cp_commit(); cp_wait<2>(); }
        else if (it + 1 < nIter) cp_wait<1>();
        else cp_wait<0>();
        __syncthreads();
        #pragma unroll
        for (int ks = 0; ks < 32; ks += 16) {
            uint32_t a[2][4], b[4][2];
            #pragma unroll
            for (int i = 0; i < 2; i++)
                ldsm_x4(a[i][0], a[i][1], a[i][2], a[i][3],
                        sm32(&As[cur][wm0 + i * 16 + (lane & 15)][ks + (lane >> 4) * 8]));
            #pragma unroll
            for (int j = 0; j < 4; j++)
                ldsm_x2t(b[j][0], b[j][1], sm32(&Bs[cur][ks + (lane & 15)][wn0 + j * 8]));
            #pragma unroll
            for (int i = 0; i < 2; i++)
                #pragma unroll
                for (int j = 0; j < 4; j++) mma16(acc[i][j], a[i], b[j]);
        }
        __syncthreads();
    }
    #pragma unroll
    for (int i = 0; i < 2; i++) {
        #pragma unroll
        for (int j = 0; j < 4; j++) {
            int r = bm + wm0 + i * 16 + (lane >> 2);
            int c = bn + wn0 + j * 8 + (lane & 3) * 2;
            #pragma unroll
            for (int hh = 0; hh < 2; hh++) {
                size_t idx = (size_t)(r + hh * 8) * N + c;
                float v0 = acc[i][j][hh * 2]     + bias[c];
                float v1 = acc[i][j][hh * 2 + 1] + bias[c + 1];
                float2 rv = *(const float2*)(resid + idx);
                float o0 = rv.x + v0 * gamma[c];
                float o1 = rv.y + v1 * gamma[c + 1];
                if (STREAM) stcs2(Cf + idx, o0, o1);
                else        *(float2*)(Cf + idx) = make_float2(o0, o1);
            }
        }
    }
}

// ---------------- Fused attention (R15 structure: qa hoisted) ----------------
__global__ void __launch_bounds__(256, 2)
attn_fused2_kernel(const __half* __restrict__ qkv, const float* __restrict__ rel_bias,
                   float* __restrict__ attnf, __half* __restrict__ o16) {
    extern __shared__ __align__(16) char dsm[];
    __half* Qs = (__half*)dsm;
    __half* St[4] = { (__half*)(dsm + 18432), (__half*)(dsm + 36864),
                      (__half*)(dsm + 55296), (__half*)(dsm + 73728) };
    __shared__ float rb_s[2 * MREL - 1];

    int bh = blockIdx.y, b = bh >> 3, h = bh & 7;
    int q0 = blockIdx.x * 128;
    int tid = threadIdx.x, lane = tid & 31, wid = tid >> 5;
    int wm0 = wid * 16;
    const float L2E = 1.44269504088896340736f;
    if (tid < 2 * MREL - 1) rb_s[tid] = rel_bias[h * (2 * MREL - 1) + tid] * L2E;

    const __half* Qg = qkv + (size_t)b * Ll * D3 + h * HD;
    const __half* Kg = Qg + Dd;
    const __half* Vg = Qg + 2 * Dd;

    {
        __half2 csc = __float2half2_rn(0.125f * L2E);
        #pragma unroll
        for (int i = 0; i < 4; i++) {
            int t = tid + i * 256;
            int r = t >> 3, s = t & 7;
            uint4 v = *(const uint4*)(Qg + (size_t)(q0 + r) * D3 + s * 8);
            __half2* hv = (__half2*)&v;
            hv[0] = __hmul2(hv[0], csc);
            hv[1] = __hmul2(hv[1], csc);
            hv[2] = __hmul2(hv[2], csc);
            hv[3] = __hmul2(hv[3], csc);
            *(uint4*)(Qs + r * 72 + s * 8) = v;
        }
    }
    __syncthreads();
    uint32_t qa[4][4];
    #pragma unroll
    for (int ks = 0; ks < 4; ks++)
        ldsm_x4(qa[ks][0], qa[ks][1], qa[ks][2], qa[ks][3],
                sm32(Qs + (wm0 + (lane & 15)) * 72 + ks * 16 + (lane >> 4) * 8));

    int rloc0 = wm0 + (lane >> 2);
    int qg0 = q0 + rloc0, qg1 = qg0 + 8;

    // Phase A: row sums only, 4-deep K pipeline
    auto loadK = [&](int kt, int st) {
        const __half* kb = Kg + (size_t)(kt * 128) * D3;
        #pragma unroll
        for (int i = 0; i < 4; i++) {
            int t = tid + i * 256;
            int r = t >> 3, s = t & 7;
            cp16(St[st] + r * 72 + s * 8, kb + (size_t)r * D3 + s * 8);
        }
    };
    loadK(0, 0); cp_commit();
    loadK(1, 1); cp_commit();
    loadK(2, 2); cp_commit();
    float esum0 = 0.f, esum1 = 0.f;
    for (int kt = 0; kt < 16; kt++) {
        if (kt + 3 < 16) { loadK(kt + 3, (kt + 3) & 3); cp_commit(); }
        if (kt < 13) cp_wait<3>();
        else if (kt == 13) cp_wait<2>();
        else if (kt == 14) cp_wait<1>();
        else cp_wait<0>();
        __syncthreads();
        __half* Kc = St[kt & 3];
        int k0 = kt * 128;
        int dt = q0 - k0;
        bool cst = (dt >= 254) || (dt <= -254);
        float rbc = (dt >= 254) ? rb_s[2 * MREL - 2] : rb_s[0];
        #pragma unroll
        for (int jp = 0; jp < 8; jp++) {
            float s2[2][4] = {};
            #pragma unroll
            for (int ks = 0; ks < 4; ks++) {
                uint32_t kb[4];
                ldsm_x4(kb[0], kb[1], kb[2], kb[3],
                        sm32(Kc + ((jp * 2 + (lane >> 4)) * 8 + (lane & 7)) * 72
                             + ks * 16 + ((lane >> 3) & 1) * 8));
                mma16(s2[0], qa[ks], &kb[0]);
                mma16(s2[1], qa[ks], &kb[2]);
            }
            #pragma unroll
            for (int t = 0; t < 2; t++) {
                int kkg = k0 + (jp * 2 + t) * 8 + (lane & 3) * 2;
                float rb00 = cst ? rbc : rb_s[clampq(qg0 - kkg)     + MREL - 1];
                float rb01 = cst ? rbc : rb_s[clampq(qg0 - kkg - 1) + MREL - 1];
                float rb10 = cst ? rbc : rb_s[clampq(qg1 - kkg)     + MREL - 1];
                float rb11 = cst ? rbc : rb_s[clampq(qg1 - kkg - 1) + MREL - 1];
                esum0 += ex2(s2[t][0] + rb00) + ex2(s2[t][1] + rb01);
                esum1 += ex2(s2[t][2] + rb10) + ex2(s2[t][3] + rb11);
            }
        }
        __syncthreads();
    }
    esum0 += __shfl_xor_sync(0xffffffffu, esum0, 1);
    esum0 += __shfl_xor_sync(0xffffffffu, esum0, 2);
    esum1 += __shfl_xor_sync(0xffffffffu, esum1, 1);
    esum1 += __shfl_xor_sync(0xffffffffu, esum1, 2);
    float inv0 = 1.0f / esum0, inv1 = 1.0f / esum1;

    // Phase B: emit p32 + O = P V (2-stage K+V)
    __half* Kbuf[2] = { St[0], St[2] };
    __half* Vbuf[2] = { St[1], St[3] };
    auto loadKV = [&](int kt, int st) {
        const __half* kb = Kg + (size_t)(kt * 128) * D3;
        const __half* vb = Vg + (size_t)(kt * 128) * D3;
        #pragma unroll
        for (int i = 0; i < 4; i++) {
            int t = tid + i * 256;
            int r = t >> 3, s = t & 7;
            cp16(Kbuf[st] + r * 72 + s * 8, kb + (size_t)r * D3 + s * 8);
            cp16(Vbuf[st] + r * 72 + s * 8, vb + (size_t)r * D3 + s * 8);
        }
    };
    loadKV(0, 0); cp_commit();
    float acc_o[8][4] = {};
    float* arow0 = attnf + ((size_t)bh * Ll + qg0) * Ll;
    float* arow1 = attnf + ((size_t)bh * Ll + qg1) * Ll;
    for (int kt = 0; kt < 16; kt++) {
        int cur = kt & 1;
        if (kt + 1 < 16) { loadKV(kt + 1, cur ^ 1); cp_commit(); cp_wait<1>(); }
        else cp_wait<0>();
        __syncthreads();
        __half* Kc = Kbuf[cur];
        __half* Vc = Vbuf[cur];
        int k0 = kt * 128;
        int dt = q0 - k0;
        bool cst = (dt >= 254) || (dt <= -254);
        float rbc = (dt >= 254) ? rb_s[2 * MREL - 2] : rb_s[0];
        #pragma unroll
        for (int jp = 0; jp < 8; jp++) {
            float s2[2][4] = {};
            #pragma unroll
            for (int ks = 0; ks < 4; ks++) {
                uint32_t kb[4];
                ldsm_x4(kb[0], kb[1], kb[2], kb[3],
                        sm32(Kc + ((jp * 2 + (lane >> 4)) * 8 + (lane & 7)) * 72
                             + ks * 16 + ((lane >> 3) & 1) * 8));
                mma16(s2[0], qa[ks], &kb[0]);
                mma16(s2[1], qa[ks], &kb[2]);
            }
            uint32_t af[4];
            #pragma unroll
            for (int t = 0; t < 2; t++) {
                int kkg = k0 + (jp * 2 + t) * 8 + (lane & 3) * 2;
                float rb00 = cst ? rbc : rb_s[clampq(qg0 - kkg)     + MREL - 1];
                float rb01 = cst ? rbc : rb_s[clampq(qg0 - kkg - 1) + MREL - 1];
                float rb10 = cst ? rbc : rb_s[clampq(qg1 - kkg)     + MREL - 1];
                float rb11 = cst ? rbc : rb_s[clampq(qg1 - kkg - 1) + MREL - 1];
                float p0 = ex2(s2[t][0] + rb00) * inv0;
                float p1 = ex2(s2[t][1] + rb01) * inv0;
                float p2 = ex2(s2[t][2] + rb10) * inv1;
                float p3 = ex2(s2[t][3] + rb11) * inv1;
                stcs2(arow0 + kkg, p0, p1);
                stcs2(arow1 + kkg, p2, p3);
                __half2 h01 = __floats2half2_rn(p0, p1);
                __half2 h23 = __floats2half2_rn(p2, p3);
                af[t * 2]     = *(uint32_t*)&h01;
                af[t * 2 + 1] = *(uint32_t*)&h23;
            }
            #pragma unroll
            for (int np = 0; np < 4; np++) {
                uint32_t vb[4];
                ldsm_x4t(vb[0], vb[1], vb[2], vb[3],
                         sm32(Vc + (jp * 16 + (lane & 7) + ((lane >> 3) & 1) * 8) * 72
                              + (np * 2 + (lane >> 4)) * 8));
                mma16(acc_o[np * 2],     af, &vb[0]);
                mma16(acc_o[np * 2 + 1], af, &vb[2]);
            }
        }
        __syncthreads();
    }
    #pragma unroll
    for (int n = 0; n < 8; n++) {
        int c = n * 8 + (lane & 3) * 2;
        __half* dst = o16 + (size_t)(b * Ll + qg0) * Dd + h * HD + c;
        *(__half2*)dst = __floats2half2_rn(acc_o[n][0], acc_o[n][1]);
        *(__half2*)(dst + (size_t)8 * Dd) = __floats2half2_rn(acc_o[n][2], acc_o[n][3]);
    }
}

// ---------------- FFN-in GEMM + fused GEGLU, BM=128, 3-stage ----------------
__global__ void gemm_geglu_kernel(const __half* __restrict__ A, const __half* __restrict__ W,
                                  const float* __restrict__ bias, __half* __restrict__ F) {
    __shared__ __half As[3][128][40];
    __shared__ __half Bs[3][2][32][72];
    int bm = blockIdx.y * 128, bn = blockIdx.x * 64;
    int tid = threadIdx.x, lane = tid & 31, wid = tid >> 5;
    int wm = (wid >> 1) * 32, wn = (wid & 1) * 32;
    float acc[2][2][4][4] = {};
    auto load = [&](int k0, int st) {
        #pragma unroll
        for (int i = 0; i < 2; i++) {
            int t = tid + i * 256;
            int r = t >> 2, s = t & 3;
            cp16(&As[st][r][s * 8], A + (size_t)(bm + r) * Dd + k0 + s * 8);
        }
        {
            int r = tid >> 3, s = tid & 7;
            #pragma unroll
            for (int hh = 0; hh < 2; hh++)
                cp16(&Bs[st][hh][r][s * 8],
                     W + (size_t)(k0 + r) * (2 * DH) + bn + hh * DH + s * 8);
        }
    };
    constexpr int NIT = Dd / 32;
    load(0, 0); cp_commit();
    load(32, 1); cp_commit();
    for (int it = 0; it < NIT; it++) {
        int cur = it % 3;
        if (it + 2 < NIT) { load((it + 2) * 32, (it + 2) % 3); cp_commit(); cp_wait<2>(); }
        else if (it + 1 < NIT) cp_wait<1>();
        else cp_wait<0>();
        __syncthreads();
        #pragma unroll
        for (int ks = 0; ks < 32; ks += 16) {
            uint32_t a[2][4];
            #pragma unroll
            for (int mi = 0; mi < 2; mi++)
                ldsm_x4(a[mi][0], a[mi][1], a[mi][2], a[mi][3],
                        sm32(&As[cur][wm + mi * 16 + (lane & 15)][ks + (lane >> 4) * 8]));
            #pragma unroll
            for (int hh = 0; hh < 2; hh++)
                #pragma unroll
                for (int nj = 0; nj < 4; nj++) {
                    uint32_t bfr[2];
                    ldsm_x2t(bfr[0], bfr[1], sm32(&Bs[cur][hh][ks + (lane & 15)][wn + nj * 8]));
                    #pragma unroll
                    for (int mi = 0; mi < 2; mi++) mma16(acc[hh][mi][nj], a[mi], bfr);
                }
        }
        __syncthreads();
    }
    #pragma unroll
    for (int mi = 0; mi < 2; mi++) {
        #pragma unroll
        for (int nj = 0; nj < 4; nj++) {
            int r = bm + wm + mi * 16 + (lane >> 2);
            int c = bn + wn + nj * 8 + (lane & 3) * 2;
            float ba0 = bias[c], ba1 = bias[c + 1];
            float bb0 = bias[c + DH], bb1 = bias[c + DH + 1];
            #pragma unroll
            for (int hh = 0; hh < 2; hh++) {
                float av0 = acc[0][mi][nj][hh * 2]     + ba0;
                float av1 = acc[0][mi][nj][hh * 2 + 1] + ba1;
                float bg0 = acc[1][mi][nj][hh * 2]     + bb0;
                float bg1 = acc[1][mi][nj][hh * 2 + 1] + bb1;
                float g0 = 0.5f * bg0 * (1.0f + erff(bg0 * 0.70710678118654752f));
                float g1 = 0.5f * bg1 * (1.0f + erff(bg1 * 0.70710678118654752f));
                size_t idx = (size_t)(r + hh * 8) * DH + c;
                *(__half2*)(F + idx) = __floats2half2_rn(g0 * av0, g1 * av1);
            }
        }
    }
}

extern "C" void kernel_launch(void* const* d_in, const int* in_sizes, int n_in,
                              void* d_out, int out_size) {
    const float* x        = (const float*)d_in[0];
    const float* ln1_w    = (const float*)d_in[1];
    const float* ln1_b    = (const float*)d_in[2];
    const float* qkv_w    = (const float*)d_in[3];
    const float* qkv_b    = (const float*)d_in[4];
    const float* out_w    = (const float*)d_in[5];
    const float* out_b    = (const float*)d_in[6];
    const float* rel_bias = (const float*)d_in[7];
    const float* gamma1   = (const float*)d_in[8];
    const float* ln2_w    = (const float*)d_in[9];
    const float* ln2_b    = (const float*)d_in[10];
    const float* ffn_in_w = (const float*)d_in[11];
    const float* ffn_in_b = (const float*)d_in[12];
    const float* ffn_out_w= (const float*)d_in[13];
    const float* ffn_out_b= (const float*)d_in[14];
    const float* gamma2   = (const float*)d_in[15];

    float* out_x = (float*)d_out;
    float* attn  = (float*)d_out + XSIZE;

    __half *h16, *qkv16, *o16, *f16, *w16;
    float *x1;
    cudaGetSymbolAddress((void**)&h16,    g_h16);
    cudaGetSymbolAddress((void**)&qkv16,  g_qkv16);
    cudaGetSymbolAddress((void**)&o16,    g_o16);
    cudaGetSymbolAddress((void**)&f16,    g_f16);
    cudaGetSymbolAddress((void**)&w16,    g_w16);
    cudaGetSymbolAddress((void**)&x1,     g_x1);

    cudaFuncSetAttribute(attn_fused2_kernel, cudaFuncAttributeMaxDynamicSharedMemorySize, 92160);

    // 0. weights fp16 + LN1 in one launch
    f2h_ln_kernel<<<4096 + BL, 256>>>((const float4*)qkv_w, (const float4*)out_w,
                                      (const float4*)ffn_in_w, (const float4*)ffn_out_w,
                                      (__half2*)w16, x, ln1_w, ln1_b, h16);
    // 1. qkv16 = h16 @ qkv_w + qkv_b
    gemm16_kernel<<<dim3(D3 / 128, BL / 128), 256>>>(h16, w16 + OFF_QKVW, qkv_b, qkv16, D3, Dd);
    // 2. fused two-phase attention: p32 -> d_out, o16
    attn_fused2_kernel<<<dim3(Ll / 128, Bb * Hh), 256, 92160>>>(qkv16, rel_bias, attn, o16);
    // 3. x1 = x + (o16 @ out_w + out_b) * gamma1  (3 CTAs/SM)
    gemm16_n512_kernel<false><<<dim3(Dd / 128, BL / 64), 256>>>(o16, w16 + OFF_OUTW, out_b, x1, x, gamma1, Dd, Dd);
    // 4. h16 = LN2(x1)
    ln_kernel<<<BL, 256>>>(x1, ln2_w, ln2_b, h16);
    // 5. f16 = geglu(h16 @ ffn_in_w + b)
    gemm_geglu_kernel<<<dim3(DH / 64, BL / 128), 256>>>(h16, w16 + OFF_FFNIN, ffn_in_b, f16);
    // 6. out_x = x1 + (f16 @ ffn_out_w + b) * gamma2  (3 CTAs/SM, streaming store)
    gemm16_n512_kernel<true><<<dim3(Dd / 128, BL / 64), 256>>>(f16, w16 + OFF_FFNOUT, ffn_out_b, out_x, x1, gamma2, Dd, DH);
}

// round 17
// speedup vs baseline: 1.0082x; 1.0082x over previous
#include <cuda_runtime.h>
#include <cuda_fp16.h>
#include <math.h>
#include <stdint.h>

// Problem constants
constexpr int Bb  = 2;
constexpr int Ll  = 2048;
constexpr int Dd  = 512;
constexpr int Hh  = 8;
constexpr int HD  = 64;
constexpr int DH  = 2048;
constexpr int MREL = 128;
constexpr int D3  = 3 * Dd;    // 1536
constexpr int BL  = Bb * Ll;   // 4096
constexpr long long XSIZE  = (long long)BL * Dd;

// fp16 staging buffers
__device__ __half g_h16  [BL * Dd];
__device__ __half g_qkv16[BL * D3];
__device__ __half g_o16  [BL * Dd];
__device__ __half g_f16  [BL * DH];
// fp16 weights: qkv_w | out_w | ffn_in_w | ffn_out_w  (contiguous)
constexpr long long OFF_QKVW   = 0;
constexpr long long OFF_OUTW   = OFF_QKVW  + (long long)Dd * D3;
constexpr long long OFF_FFNIN  = OFF_OUTW  + (long long)Dd * Dd;
constexpr long long OFF_FFNOUT = OFF_FFNIN + (long long)Dd * 2 * DH;
constexpr long long W16_TOTAL  = OFF_FFNOUT + (long long)DH * Dd;   // 4,194,304
__device__ __half g_w16[W16_TOTAL];
__device__ float  g_x1  [BL * Dd];

// ---------------- helpers ----------------
static __device__ __forceinline__ uint32_t sm32(const void* p) {
    return (uint32_t)__cvta_generic_to_shared(p);
}
static __device__ __forceinline__ void cp16(void* dst, const void* src) {
    asm volatile("cp.async.cg.shared.global [%0], [%1], 16;\n"
                 :: "r"(sm32(dst)), "l"(__cvta_generic_to_global(src)));
}
static __device__ __forceinline__ void cp_commit() {
    asm volatile("cp.async.commit_group;\n");
}
template <int N> static __device__ __forceinline__ void cp_wait() {
    asm volatile("cp.async.wait_group %0;\n" :: "n"(N));
}
static __device__ __forceinline__ void ldsm_x4(uint32_t& r0, uint32_t& r1, uint32_t& r2, uint32_t& r3, uint32_t a) {
    asm volatile("ldmatrix.sync.aligned.m8n8.x4.shared.b16 {%0,%1,%2,%3}, [%4];\n"
                 : "=r"(r0), "=r"(r1), "=r"(r2), "=r"(r3) : "r"(a));
}
static __device__ __forceinline__ void ldsm_x4t(uint32_t& r0, uint32_t& r1, uint32_t& r2, uint32_t& r3, uint32_t a) {
    asm volatile("ldmatrix.sync.aligned.m8n8.x4.trans.shared.b16 {%0,%1,%2,%3}, [%4];\n"
                 : "=r"(r0), "=r"(r1), "=r"(r2), "=r"(r3) : "r"(a));
}
static __device__ __forceinline__ void ldsm_x2t(uint32_t& r0, uint32_t& r1, uint32_t a) {
    asm volatile("ldmatrix.sync.aligned.m8n8.x2.trans.shared.b16 {%0,%1}, [%2];\n"
                 : "=r"(r0), "=r"(r1) : "r"(a));
}
static __device__ __forceinline__ void mma16(float* c, const uint32_t* a, const uint32_t* b) {
    asm volatile("mma.sync.aligned.m16n8k16.row.col.f32.f16.f16.f32 "
                 "{%0,%1,%2,%3}, {%4,%5,%6,%7}, {%8,%9}, {%0,%1,%2,%3};\n"
                 : "+f"(c[0]), "+f"(c[1]), "+f"(c[2]), "+f"(c[3])
                 : "r"(a[0]), "r"(a[1]), "r"(a[2]), "r"(a[3]), "r"(b[0]), "r"(b[1]));
}
static __device__ __forceinline__ float ex2(float x) {
    float r;
    asm("ex2.approx.f32 %0, %1;" : "=f"(r) : "f"(x));
    return r;
}
static __device__ __forceinline__ void stcs2(float* p, float a, float b) {
    asm volatile("st.global.cs.v2.f32 [%0], {%1, %2};"
                 :: "l"(__cvta_generic_to_global(p)), "f"(a), "f"(b) : "memory");
}
static __device__ __forceinline__ int clampq(int d) {
    return d < -(MREL - 1) ? -(MREL - 1) : (d > (MREL - 1) ? (MREL - 1) : d);
}

// ---------------- merged: weights fp32->fp16 + LN1, one launch ----------------
constexpr long long E0 = OFF_OUTW   / 4;
constexpr long long E1 = OFF_FFNIN  / 4;
constexpr long long E2 = OFF_FFNOUT / 4;
constexpr long long E3 = W16_TOTAL  / 4;
__global__ void f2h_ln_kernel(const float4* __restrict__ wa, const float4* __restrict__ wb,
                              const float4* __restrict__ wc, const float4* __restrict__ wd,
                              __half2* __restrict__ wdst,
                              const float* __restrict__ x, const float* __restrict__ lw,
                              const float* __restrict__ lb, __half* __restrict__ hout) {
    if (blockIdx.x < 4096) {
        long long i = (long long)blockIdx.x * 256 + threadIdx.x;
        const float4* src; long long off;
        if (i < E0)      { src = wa; off = 0;  }
        else if (i < E1) { src = wb; off = E0; }
        else if (i < E2) { src = wc; off = E1; }
        else             { src = wd; off = E2; }
        float4 v = src[i - off];
        wdst[i * 2]     = __floats2half2_rn(v.x, v.y);
        wdst[i * 2 + 1] = __floats2half2_rn(v.z, v.w);
        return;
    }
    int row = blockIdx.x - 4096;
    const float* xr = x + (long long)row * Dd;
    int t = threadIdx.x;
    float v0 = xr[t], v1 = xr[t + 256];
    __shared__ float red[256];
    red[t] = v0 + v1;
    __syncthreads();
    #pragma unroll
    for (int o = 128; o > 0; o >>= 1) { if (t < o) red[t] += red[t + o]; __syncthreads(); }
    float mu = red[0] * (1.0f / Dd);
    __syncthreads();
    float d0 = v0 - mu, d1 = v1 - mu;
    red[t] = d0 * d0 + d1 * d1;
    __syncthreads();
    #pragma unroll
    for (int o = 128; o > 0; o >>= 1) { if (t < o) red[t] += red[t + o]; __syncthreads(); }
    float rstd = rsqrtf(red[0] * (1.0f / Dd) + 1e-5f);
    __half* orow = hout + (long long)row * Dd;
    orow[t]       = __float2half(d0 * rstd * lw[t]       + lb[t]);
    orow[t + 256] = __float2half(d1 * rstd * lw[t + 256] + lb[t + 256]);
}

// ---------------- LayerNorm -> fp16 out ----------------
__global__ void ln_kernel(const float* __restrict__ x, const float* __restrict__ w,
                          const float* __restrict__ b, __half* __restrict__ out) {
    int row = blockIdx.x;
    const float* xr = x + (long long)row * Dd;
    int t = threadIdx.x;
    float v0 = xr[t], v1 = xr[t + 256];
    __shared__ float red[256];
    red[t] = v0 + v1;
    __syncthreads();
    #pragma unroll
    for (int o = 128; o > 0; o >>= 1) { if (t < o) red[t] += red[t + o]; __syncthreads(); }
    float mu = red[0] * (1.0f / Dd);
    __syncthreads();
    float d0 = v0 - mu, d1 = v1 - mu;
    red[t] = d0 * d0 + d1 * d1;
    __syncthreads();
    #pragma unroll
    for (int o = 128; o > 0; o >>= 1) { if (t < o) red[t] += red[t + o]; __syncthreads(); }
    float rstd = rsqrtf(red[0] * (1.0f / Dd) + 1e-5f);
    __half* orow = out + (long long)row * Dd;
    orow[t]       = __float2half(d0 * rstd * w[t]       + b[t]);
    orow[t + 256] = __float2half(d1 * rstd * w[t + 256] + b[t + 256]);
}

// ---------------- BM=128 GEMM, half out, 3-stage (QKV) ----------------
__global__ void gemm16_kernel(const __half* __restrict__ A, const __half* __restrict__ W,
                              const float* __restrict__ bias, __half* __restrict__ Ch,
                              int N, int K) {
    __shared__ __half As[3][128][40];
    __shared__ __half Bs[3][32][136];
    int bm = blockIdx.y * 128, bn = blockIdx.x * 128;
    int tid = threadIdx.x, lane = tid & 31, wid = tid >> 5;
    int wm0 = (wid & 1) * 64, wn0 = (wid >> 1) * 32;

    auto load = [&](int k0, int st) {
        #pragma unroll
        for (int i = 0; i < 2; i++) {
            int t = tid + i * 256;
            int r = t >> 2, s = t & 3;
            cp16(&As[st][r][s * 8], A + (size_t)(bm + r) * K + k0 + s * 8);
        }
        #pragma unroll
        for (int i = 0; i < 2; i++) {
            int t = tid + i * 256;
            int r = t >> 4, s = t & 15;
            cp16(&Bs[st][r][s * 8], W + (size_t)(k0 + r) * N + bn + s * 8);
        }
    };
    int nIter = K / 32;
    load(0, 0); cp_commit();
    if (nIter > 1) { load(32, 1); cp_commit(); }
    float acc[4][4][4] = {};
    for (int it = 0; it < nIter; it++) {
        int cur = it % 3;
        if (it + 2 < nIter) { load((it + 2) * 32, (it + 2) % 3); cp_commit(); cp_wait<2>(); }
        else if (it + 1 < nIter) cp_wait<1>();
        else cp_wait<0>();
        __syncthreads();
        #pragma unroll
        for (int ks = 0; ks < 32; ks += 16) {
            uint32_t a[4][4], b[4][2];
            #pragma unroll
            for (int i = 0; i < 4; i++)
                ldsm_x4(a[i][0], a[i][1], a[i][2], a[i][3],
                        sm32(&As[cur][wm0 + i * 16 + (lane & 15)][ks + (lane >> 4) * 8]));
            #pragma unroll
            for (int j = 0; j < 4; j++)
                ldsm_x2t(b[j][0], b[j][1], sm32(&Bs[cur][ks + (lane & 15)][wn0 + j * 8]));
            #pragma unroll
            for (int i = 0; i < 4; i++)
                #pragma unroll
                for (int j = 0; j < 4; j++) mma16(acc[i][j], a[i], b[j]);
        }
        __syncthreads();
    }
    #pragma unroll
    for (int i = 0; i < 4; i++) {
        #pragma unroll
        for (int j = 0; j < 4; j++) {
            int r = bm + wm0 + i * 16 + (lane >> 2);
            int c = bn + wn0 + j * 8 + (lane & 3) * 2;
            #pragma unroll
            for (int hh = 0; hh < 2; hh++) {
                size_t idx = (size_t)(r + hh * 8) * N + c;
                float v0 = acc[i][j][hh * 2]     + bias[c];
                float v1 = acc[i][j][hh * 2 + 1] + bias[c + 1];
                *(__half2*)(Ch + idx) = __floats2half2_rn(v0, v1);
            }
        }
    }
}

// ---------------- BM=64 GEMM for N=512, MODE1 epilogue, 2-stage, 3 CTAs/SM ----------------
// 2-stage keeps smem at 27.6 KB/CTA so 3 CTAs actually fit.
template <bool STREAM>
__global__ void __launch_bounds__(256, 3)
gemm16_n512_kernel(const __half* __restrict__ A, const __half* __restrict__ W,
                   const float* __restrict__ bias, float* __restrict__ Cf,
                   const float* __restrict__ resid, const float* __restrict__ gamma,
                   int N, int K) {
    __shared__ __half As[2][64][40];
    __shared__ __half Bs[2][32][136];
    int bm = blockIdx.y * 64, bn = blockIdx.x * 128;
    int tid = threadIdx.x, lane = tid & 31, wid = tid >> 5;
    int wm0 = (wid & 1) * 32, wn0 = (wid >> 1) * 32;

    auto load = [&](int k0, int st) {
        {
            int r = tid >> 2, s = tid & 3;
            cp16(&As[st][r][s * 8], A + (size_t)(bm + r) * K + k0 + s * 8);
        }
        #pragma unroll
        for (int i = 0; i < 2; i++) {
            int t = tid + i * 256;
            int r = t >> 4, s = t & 15;
            cp16(&Bs[st][r][s * 8], W + (size_t)(k0 + r) * N + bn + s * 8);
        }
    };
    int nIter = K / 32;
    load(0, 0); cp_commit();
    float acc[2][4][4] = {};
    for (int it = 0; it < nIter; it++) {
        int cur = it & 1;
        if (it + 1 < nIter) { load((it + 1) * 32, cur ^ 1); cp_commit(); cp_wait<1>(); }
        else cp_wait<0>();
        __syncthreads();
        #pragma unroll
        for (int ks = 0; ks < 32; ks += 16) {
            uint32_t a[2][4], b[4][2];
            #pragma unroll
            for (int i = 0; i < 2; i++)
                ldsm_x4(a[i][0], a[i][1], a[i][2], a[i][3],
                        sm32(&As[cur][wm0 + i * 16 + (lane & 15)][ks + (lane >> 4) * 8]));
            #pragma unroll
            for (int j = 0; j < 4; j++)
                ldsm_x2t(b[j][0], b[j][1], sm32(&Bs[cur][ks + (lane & 15)][wn0 + j * 8]));
            #pragma unroll
            for (int i = 0; i < 2; i++)
                #pragma unroll
                for (int j = 0; j < 4; j++) mma16(acc[i][j], a[i], b[j]);
        }
        __syncthreads();
    }
    #pragma unroll
    for (int i = 0; i < 2; i++) {
        #pragma unroll
        for (int j = 0; j < 4; j++) {
            int r = bm + wm0 + i * 16 + (lane >> 2);
            int c = bn + wn0 + j * 8 + (lane & 3) * 2;
            #pragma unroll
            for (int hh = 0; hh < 2; hh++) {
                size_t idx = (size_t)(r + hh * 8) * N + c;
                float v0 = acc[i][j][hh * 2]     + bias[c];
                float v1 = acc[i][j][hh * 2 + 1] + bias[c + 1];
                float2 rv = *(const float2*)(resid + idx);
                float o0 = rv.x + v0 * gamma[c];
                float o1 = rv.y + v1 * gamma[c + 1];
                if (STREAM) stcs2(Cf + idx, o0, o1);
                else        *(float2*)(Cf + idx) = make_float2(o0, o1);
            }
        }
    }
}

// ---------------- Fused attention (R15 structure: qa hoisted) ----------------
__global__ void __launch_bounds__(256, 2)
attn_fused2_kernel(const __half* __restrict__ qkv, const float* __restrict__ rel_bias,
                   float* __restrict__ attnf, __half* __restrict__ o16) {
    extern __shared__ __align__(16) char dsm[];
    __half* Qs = (__half*)dsm;
    __half* St[4] = { (__half*)(dsm + 18432), (__half*)(dsm + 36864),
                      (__half*)(dsm + 55296), (__half*)(dsm + 73728) };
    __shared__ float rb_s[2 * MREL - 1];

    int bh = blockIdx.y, b = bh >> 3, h = bh & 7;
    int q0 = blockIdx.x * 128;
    int tid = threadIdx.x, lane = tid & 31, wid = tid >> 5;
    int wm0 = wid * 16;
    const float L2E = 1.44269504088896340736f;
    if (tid < 2 * MREL - 1) rb_s[tid] = rel_bias[h * (2 * MREL - 1) + tid] * L2E;

    const __half* Qg = qkv + (size_t)b * Ll * D3 + h * HD;
    const __half* Kg = Qg + Dd;
    const __half* Vg = Qg + 2 * Dd;

    {
        __half2 csc = __float2half2_rn(0.125f * L2E);
        #pragma unroll
        for (int i = 0; i < 4; i++) {
            int t = tid + i * 256;
            int r = t >> 3, s = t & 7;
            uint4 v = *(const uint4*)(Qg + (size_t)(q0 + r) * D3 + s * 8);
            __half2* hv = (__half2*)&v;
            hv[0] = __hmul2(hv[0], csc);
            hv[1] = __hmul2(hv[1], csc);
            hv[2] = __hmul2(hv[2], csc);
            hv[3] = __hmul2(hv[3], csc);
            *(uint4*)(Qs + r * 72 + s * 8) = v;
        }
    }
    __syncthreads();
    uint32_t qa[4][4];
    #pragma unroll
    for (int ks = 0; ks < 4; ks++)
        ldsm_x4(qa[ks][0], qa[ks][1], qa[ks][2], qa[ks][3],
                sm32(Qs + (wm0 + (lane & 15)) * 72 + ks * 16 + (lane >> 4) * 8));

    int rloc0 = wm0 + (lane >> 2);
    int qg0 = q0 + rloc0, qg1 = qg0 + 8;

    // Phase A: row sums only, 4-deep K pipeline
    auto loadK = [&](int kt, int st) {
        const __half* kb = Kg + (size_t)(kt * 128) * D3;
        #pragma unroll
        for (int i = 0; i < 4; i++) {
            int t = tid + i * 256;
            int r = t >> 3, s = t & 7;
            cp16(St[st] + r * 72 + s * 8, kb + (size_t)r * D3 + s * 8);
        }
    };
    loadK(0, 0); cp_commit();
    loadK(1, 1); cp_commit();
    loadK(2, 2); cp_commit();
    float esum0 = 0.f, esum1 = 0.f;
    for (int kt = 0; kt < 16; kt++) {
        if (kt + 3 < 16) { loadK(kt + 3, (kt + 3) & 3); cp_commit(); }
        if (kt < 13) cp_wait<3>();
        else if (kt == 13) cp_wait<2>();
        else if (kt == 14) cp_wait<1>();
        else cp_wait<0>();
        __syncthreads();
        __half* Kc = St[kt & 3];
        int k0 = kt * 128;
        int dt = q0 - k0;
        bool cst = (dt >= 254) || (dt <= -254);
        float rbc = (dt >= 254) ? rb_s[2 * MREL - 2] : rb_s[0];
        #pragma unroll
        for (int jp = 0; jp < 8; jp++) {
            float s2[2][4] = {};
            #pragma unroll
            for (int ks = 0; ks < 4; ks++) {
                uint32_t kb[4];
                ldsm_x4(kb[0], kb[1], kb[2], kb[3],
                        sm32(Kc + ((jp * 2 + (lane >> 4)) * 8 + (lane & 7)) * 72
                             + ks * 16 + ((lane >> 3) & 1) * 8));
                mma16(s2[0], qa[ks], &kb[0]);
                mma16(s2[1], qa[ks], &kb[2]);
            }
            #pragma unroll
            for (int t = 0; t < 2; t++) {
                int kkg = k0 + (jp * 2 + t) * 8 + (lane & 3) * 2;
                float rb00 = cst ? rbc : rb_s[clampq(qg0 - kkg)     + MREL - 1];
                float rb01 = cst ? rbc : rb_s[clampq(qg0 - kkg - 1) + MREL - 1];
                float rb10 = cst ? rbc : rb_s[clampq(qg1 - kkg)     + MREL - 1];
                float rb11 = cst ? rbc : rb_s[clampq(qg1 - kkg - 1) + MREL - 1];
                esum0 += ex2(s2[t][0] + rb00) + ex2(s2[t][1] + rb01);
                esum1 += ex2(s2[t][2] + rb10) + ex2(s2[t][3] + rb11);
            }
        }
        __syncthreads();
    }
    esum0 += __shfl_xor_sync(0xffffffffu, esum0, 1);
    esum0 += __shfl_xor_sync(0xffffffffu, esum0, 2);
    esum1 += __shfl_xor_sync(0xffffffffu, esum1, 1);
    esum1 += __shfl_xor_sync(0xffffffffu, esum1, 2);
    float inv0 = 1.0f / esum0, inv1 = 1.0f / esum1;

    // Phase B: emit p32 + O = P V (2-stage K+V)
    __half* Kbuf[2] = { St[0], St[2] };
    __half* Vbuf[2] = { St[1], St[3] };
    auto loadKV = [&](int kt, int st) {
        const __half* kb = Kg + (size_t)(kt * 128) * D3;
        const __half* vb = Vg + (size_t)(kt * 128) * D3;
        #pragma unroll
        for (int i = 0; i < 4; i++) {
            int t = tid + i * 256;
            int r = t >> 3, s = t & 7;
            cp16(Kbuf[st] + r * 72 + s * 8, kb + (size_t)r * D3 + s * 8);
            cp16(Vbuf[st] + r * 72 + s * 8, vb + (size_t)r * D3 + s * 8);
        }
    };
    loadKV(0, 0); cp_commit();
    float acc_o[8][4] = {};
    float* arow0 = attnf + ((size_t)bh * Ll + qg0) * Ll;
    float* arow1 = attnf + ((size_t)bh * Ll + qg1) * Ll;
    for (int kt = 0; kt < 16; kt++) {
        int cur = kt & 1;
        if (kt + 1 < 16) { loadKV(kt + 1, cur ^ 1); cp_commit(); cp_wait<1>(); }
        else cp_wait<0>();
        __syncthreads();
        __half* Kc = Kbuf[cur];
        __half* Vc = Vbuf[cur];
        int k0 = kt * 128;
        int dt = q0 - k0;
        bool cst = (dt >= 254) || (dt <= -254);
        float rbc = (dt >= 254) ? rb_s[2 * MREL - 2] : rb_s[0];
        #pragma unroll
        for (int jp = 0; jp < 8; jp++) {
            float s2[2][4] = {};
            #pragma unroll
            for (int ks = 0; ks < 4; ks++) {
                uint32_t kb[4];
                ldsm_x4(kb[0], kb[1], kb[2], kb[3],
                        sm32(Kc + ((jp * 2 + (lane >> 4)) * 8 + (lane & 7)) * 72
                             + ks * 16 + ((lane >> 3) & 1) * 8));
                mma16(s2[0], qa[ks], &kb[0]);
                mma16(s2[1], qa[ks], &kb[2]);
            }
            uint32_t af[4];
            #pragma unroll
            for (int t = 0; t < 2; t++) {
                int kkg = k0 + (jp * 2 + t) * 8 + (lane & 3) * 2;
                float rb00 = cst ? rbc : rb_s[clampq(qg0 - kkg)     + MREL - 1];
                float rb01 = cst ? rbc : rb_s[clampq(qg0 - kkg - 1) + MREL - 1];
                float rb10 = cst ? rbc : rb_s[clampq(qg1 - kkg)     + MREL - 1];
                float rb11 = cst ? rbc : rb_s[clampq(qg1 - kkg - 1) + MREL - 1];
                float p0 = ex2(s2[t][0] + rb00) * inv0;
                float p1 = ex2(s2[t][1] + rb01) * inv0;
                float p2 = ex2(s2[t][2] + rb10) * inv1;
                float p3 = ex2(s2[t][3] + rb11) * inv1;
                stcs2(arow0 + kkg, p0, p1);
                stcs2(arow1 + kkg, p2, p3);
                __half2 h01 = __floats2half2_rn(p0, p1);
                __half2 h23 = __floats2half2_rn(p2, p3);
                af[t * 2]     = *(uint32_t*)&h01;
                af[t * 2 + 1] = *(uint32_t*)&h23;
            }
            #pragma unroll
            for (int np = 0; np < 4; np++) {
                uint32_t vb[4];
                ldsm_x4t(vb[0], vb[1], vb[2], vb[3],
                         sm32(Vc + (jp * 16 + (lane & 7) + ((lane >> 3) & 1) * 8) * 72
                              + (np * 2 + (lane >> 4)) * 8));
                mma16(acc_o[np * 2],     af, &vb[0]);
                mma16(acc_o[np * 2 + 1], af, &vb[2]);
            }
        }
        __syncthreads();
    }
    #pragma unroll
    for (int n = 0; n < 8; n++) {
        int c = n * 8 + (lane & 3) * 2;
        __half* dst = o16 + (size_t)(b * Ll + qg0) * Dd + h * HD + c;
        *(__half2*)dst = __floats2half2_rn(acc_o[n][0], acc_o[n][1]);
        *(__half2*)(dst + (size_t)8 * Dd) = __floats2half2_rn(acc_o[n][2], acc_o[n][3]);
    }
}

// ---------------- FFN-in GEMM + fused GEGLU, BM=128, 3-stage ----------------
__global__ void gemm_geglu_kernel(const __half* __restrict__ A, const __half* __restrict__ W,
                                  const float* __restrict__ bias, __half* __restrict__ F) {
    __shared__ __half As[3][128][40];
    __shared__ __half Bs[3][2][32][72];
    int bm = blockIdx.y * 128, bn = blockIdx.x * 64;
    int tid = threadIdx.x, lane = tid & 31, wid = tid >> 5;
    int wm = (wid >> 1) * 32, wn = (wid & 1) * 32;
    float acc[2][2][4][4] = {};
    auto load = [&](int k0, int st) {
        #pragma unroll
        for (int i = 0; i < 2; i++) {
            int t = tid + i * 256;
            int r = t >> 2, s = t & 3;
            cp16(&As[st][r][s * 8], A + (size_t)(bm + r) * Dd + k0 + s * 8);
        }
        {
            int r = tid >> 3, s = tid & 7;
            #pragma unroll
            for (int hh = 0; hh < 2; hh++)
                cp16(&Bs[st][hh][r][s * 8],
                     W + (size_t)(k0 + r) * (2 * DH) + bn + hh * DH + s * 8);
        }
    };
    constexpr int NIT = Dd / 32;
    load(0, 0); cp_commit();
    load(32, 1); cp_commit();
    for (int it = 0; it < NIT; it++) {
        int cur = it % 3;
        if (it + 2 < NIT) { load((it + 2) * 32, (it + 2) % 3); cp_commit(); cp_wait<2>(); }
        else if (it + 1 < NIT) cp_wait<1>();
        else cp_wait<0>();
        __syncthreads();
        #pragma unroll
        for (int ks = 0; ks < 32; ks += 16) {
            uint32_t a[2][4];
            #pragma unroll
            for (int mi = 0; mi < 2; mi++)
                ldsm_x4(a[mi][0], a[mi][1], a[mi][2], a[mi][3],
                        sm32(&As[cur][wm + mi * 16 + (lane & 15)][ks + (lane >> 4) * 8]));
            #pragma unroll
            for (int hh = 0; hh < 2; hh++)
                #pragma unroll
                for (int nj = 0; nj < 4; nj++) {
                    uint32_t bfr[2];
                    ldsm_x2t(bfr[0], bfr[1], sm32(&Bs[cur][hh][ks + (lane & 15)][wn + nj * 8]));
                    #pragma unroll
                    for (int mi = 0; mi < 2; mi++) mma16(acc[hh][mi][nj], a[mi], bfr);
                }
        }
        __syncthreads();
    }
    #pragma unroll
    for (int mi = 0; mi < 2; mi++) {
        #pragma unroll
        for (int nj = 0; nj < 4; nj++) {
            int r = bm + wm + mi * 16 + (lane >> 2);
            int c = bn + wn + nj * 8 + (lane & 3) * 2;
            float ba0 = bias[c], ba1 = bias[c + 1];
            float bb0 = bias[c + DH], bb1 = bias[c + DH + 1];
            #pragma unroll
            for (int hh = 0; hh < 2; hh++) {
                float av0 = acc[0][mi][nj][hh * 2]     + ba0;
                float av1 = acc[0][mi][nj][hh * 2 + 1] + ba1;
                float bg0 = acc[1][mi][nj][hh * 2]     + bb0;
                float bg1 = acc[1][mi][nj][hh * 2 + 1] + bb1;
                float g0 = 0.5f * bg0 * (1.0f + erff(bg0 * 0.70710678118654752f));
                float g1 = 0.5f * bg1 * (1.0f + erff(bg1 * 0.70710678118654752f));
                size_t idx = (size_t)(r + hh * 8) * DH + c;
                *(__half2*)(F + idx) = __floats2half2_rn(g0 * av0, g1 * av1);
            }
        }
    }
}

extern "C" void kernel_launch(void* const* d_in, const int* in_sizes, int n_in,
                              void* d_out, int out_size) {
    const float* x        = (const float*)d_in[0];
    const float* ln1_w    = (const float*)d_in[1];
    const float* ln1_b    = (const float*)d_in[2];
    const float* qkv_w    = (const float*)d_in[3];
    const float* qkv_b    = (const float*)d_in[4];
    const float* out_w    = (const float*)d_in[5];
    const float* out_b    = (const float*)d_in[6];
    const float* rel_bias = (const float*)d_in[7];
    const float* gamma1   = (const float*)d_in[8];
    const float* ln2_w    = (const float*)d_in[9];
    const float* ln2_b    = (const float*)d_in[10];
    const float* ffn_in_w = (const float*)d_in[11];
    const float* ffn_in_b = (const float*)d_in[12];
    const float* ffn_out_w= (const float*)d_in[13];
    const float* ffn_out_b= (const float*)d_in[14];
    const float* gamma2   = (const float*)d_in[15];

    float* out_x = (float*)d_out;
    float* attn  = (float*)d_out + XSIZE;

    __half *h16, *qkv16, *o16, *f16, *w16;
    float *x1;
    cudaGetSymbolAddress((void**)&h16,    g_h16);
    cudaGetSymbolAddress((void**)&qkv16,  g_qkv16);
    cudaGetSymbolAddress((void**)&o16,    g_o16);
    cudaGetSymbolAddress((void**)&f16,    g_f16);
    cudaGetSymbolAddress((void**)&w16,    g_w16);
    cudaGetSymbolAddress((void**)&x1,     g_x1);

    cudaFuncSetAttribute(attn_fused2_kernel, cudaFuncAttributeMaxDynamicSharedMemorySize, 92160);

    // 0. weights fp16 + LN1 in one launch
    f2h_ln_kernel<<<4096 + BL, 256>>>((const float4*)qkv_w, (const float4*)out_w,
                                      (const float4*)ffn_in_w, (const float4*)ffn_out_w,
                                      (__half2*)w16, x, ln1_w, ln1_b, h16);
    // 1. qkv16 = h16 @ qkv_w + qkv_b
    gemm16_kernel<<<dim3(D3 / 128, BL / 128), 256>>>(h16, w16 + OFF_QKVW, qkv_b, qkv16, D3, Dd);
    // 2. fused two-phase attention: p32 -> d_out, o16
    attn_fused2_kernel<<<dim3(Ll / 128, Bb * Hh), 256, 92160>>>(qkv16, rel_bias, attn, o16);
    // 3. x1 = x + (o16 @ out_w + out_b) * gamma1  (2-stage, 3 CTAs/SM)
    gemm16_n512_kernel<false><<<dim3(Dd / 128, BL / 64), 256>>>(o16, w16 + OFF_OUTW, out_b, x1, x, gamma1, Dd, Dd);
    // 4. h16 = LN2(x1)
    ln_kernel<<<BL, 256>>>(x1, ln2_w, ln2_b, h16);
    // 5. f16 = geglu(h16 @ ffn_in_w + b)
    gemm_geglu_kernel<<<dim3(DH / 64, BL / 128), 256>>>(h16, w16 + OFF_FFNIN, ffn_in_b, f16);
    // 6. out_x = x1 + (f16 @ ffn_out_w + b) * gamma2  (2-stage, 3 CTAs/SM, streaming store)
    gemm16_n512_kernel<true><<<dim3(Dd / 128, BL / 64), 256>>>(f16, w16 + OFF_FFNOUT, ffn_out_b, out_x, x1, gamma2, Dd, DH);
}